// round 15
// baseline (speedup 1.0000x reference)
#include <cuda_runtime.h>
#include <cuda_bf16.h>
#include <cstdint>
#include <cstdio>

// ---------------- problem constants ----------------
#define NL    12
#define DMODEL 768
#define NHEAD 12
#define DHEAD 64
#define DMLP  3072
#define NTOK  577
#define NPATCH 576
#define BATCH 32
#define ROWS  (BATCH*NTOK)     // 18464
#define PROWS (BATCH*NPATCH)   // 18432
#define OUTN  1000

// ---------------- scratch (device globals; no allocation allowed) ----------------
__device__ float g_X [ROWS*DMODEL];
__device__ float g_Y [ROWS*DMODEL];
__device__ float g_Z [ROWS*DMODEL];
__device__ float g_Q [ROWS*DMODEL];
__device__ float g_K [ROWS*DMODEL];
__device__ float g_V [ROWS*DMODEL];
__device__ float g_VH[ROWS*DMODEL];
__device__ float g_H [ROWS*DMLP];              // also reused as patch buffer
__device__ float g_S [127844736UL];            // 32*12*577*577 scores

// ---------------- GEMM params ----------------
struct GP {
    const float *A, *B; float *C;
    const float *bias, *res;
    int M, N, K, lda, ldb, ldc;
    int divA; long long sA1, sA2;
    int divB; long long sB1, sB2;
    int divC; long long sC1, sC2;
    int gelu;
};

// ---------------- PTX helpers ----------------
__device__ __forceinline__ void ldsm4(uint32_t &r0, uint32_t &r1, uint32_t &r2, uint32_t &r3,
                                      const __nv_bfloat16* p) {
    uint32_t a = (uint32_t)__cvta_generic_to_shared(p);
    asm volatile("ldmatrix.sync.aligned.m8n8.x4.shared.b16 {%0,%1,%2,%3},[%4];\n"
                 : "=r"(r0), "=r"(r1), "=r"(r2), "=r"(r3) : "r"(a));
}
__device__ __forceinline__ void ldsm4t(uint32_t &r0, uint32_t &r1, uint32_t &r2, uint32_t &r3,
                                       const __nv_bfloat16* p) {
    uint32_t a = (uint32_t)__cvta_generic_to_shared(p);
    asm volatile("ldmatrix.sync.aligned.m8n8.x4.trans.shared.b16 {%0,%1,%2,%3},[%4];\n"
                 : "=r"(r0), "=r"(r1), "=r"(r2), "=r"(r3) : "r"(a));
}
__device__ __forceinline__ void mma_bf16(float c[4], const uint32_t a[4], const uint32_t b[2]) {
    asm volatile("mma.sync.aligned.m16n8k16.row.col.f32.bf16.bf16.f32 "
                 "{%0,%1,%2,%3},{%4,%5,%6,%7},{%8,%9},{%0,%1,%2,%3};\n"
                 : "+f"(c[0]), "+f"(c[1]), "+f"(c[2]), "+f"(c[3])
                 : "r"(a[0]), "r"(a[1]), "r"(a[2]), "r"(a[3]), "r"(b[0]), "r"(b[1]));
}
// split fp32 pair into bf16 hi/lo packed u32s
__device__ __forceinline__ void split2(float x0, float x1, uint32_t &hi, uint32_t &lo) {
    __nv_bfloat16 h0 = __float2bfloat16(x0);
    __nv_bfloat16 h1 = __float2bfloat16(x1);
    float r0 = x0 - __bfloat162float(h0);
    float r1 = x1 - __bfloat162float(h1);
    __nv_bfloat162 hv = __halves2bfloat162(h0, h1);
    __nv_bfloat162 lv = __halves2bfloat162(__float2bfloat16(r0), __float2bfloat16(r1));
    hi = *reinterpret_cast<uint32_t*>(&hv);
    lo = *reinterpret_cast<uint32_t*>(&lv);
}

// ---------------- GEMM kernel: C = A*B (+bias)(+res)(gelu), bf16x3 precision ----------------
// TB=false: B global is [K,N] row-major (NN).  TB=true: B global is [N,K] row-major (NT, C=A*B^T)
template<bool TB>
__global__ void __launch_bounds__(256) gemm_k(GP p) {
    constexpr int BM = 128, BN = 64, BK = 32;
    __shared__ alignas(16) __nv_bfloat16 Ah[BM][BK + 8];
    __shared__ alignas(16) __nv_bfloat16 Al[BM][BK + 8];
    constexpr int BR  = TB ? BN : BK;
    constexpr int BCW = TB ? (BK + 8) : (BN + 8);
    __shared__ alignas(16) __nv_bfloat16 Bh[BR][BCW];
    __shared__ alignas(16) __nv_bfloat16 Bl[BR][BCW];

    const int tid = threadIdx.x, lane = tid & 31, warp = tid >> 5;
    const int wm0 = (warp & 3) * 32, wn0 = (warp >> 2) * 32;
    const int n0 = blockIdx.x * BN, m0 = blockIdx.y * BM;
    const int z = blockIdx.z;

    const float* A = p.A + (long long)(z / p.divA) * p.sA1 + (long long)(z % p.divA) * p.sA2;
    const float* B = p.B + (long long)(z / p.divB) * p.sB1 + (long long)(z % p.divB) * p.sB2;
    float*       C = p.C + (long long)(z / p.divC) * p.sC1 + (long long)(z % p.divC) * p.sC2;

    float acc[2][4][4];
#pragma unroll
    for (int a = 0; a < 2; a++)
#pragma unroll
        for (int b = 0; b < 4; b++)
#pragma unroll
            for (int c = 0; c < 4; c++) acc[a][b][c] = 0.f;

    for (int k0 = 0; k0 < p.K; k0 += BK) {
        // ---- load A tile [BM][BK] ----
#pragma unroll
        for (int i = 0; i < 4; i++) {
            int r = (tid >> 3) + i * 32;
            int c4 = (tid & 7) * 4;
            int gm = m0 + r, gk = k0 + c4;
            float x0 = 0.f, x1 = 0.f, x2 = 0.f, x3 = 0.f;
            if (gm < p.M) {
                const float* ap = A + (size_t)gm * p.lda + gk;
                if (gk + 3 < p.K && ((((size_t)ap) & 15) == 0)) {
                    float4 v = *reinterpret_cast<const float4*>(ap);
                    x0 = v.x; x1 = v.y; x2 = v.z; x3 = v.w;
                } else {
                    if (gk     < p.K) x0 = ap[0];
                    if (gk + 1 < p.K) x1 = ap[1];
                    if (gk + 2 < p.K) x2 = ap[2];
                    if (gk + 3 < p.K) x3 = ap[3];
                }
            }
            uint32_t h, l;
            split2(x0, x1, h, l);
            *reinterpret_cast<uint32_t*>(&Ah[r][c4])     = h;
            *reinterpret_cast<uint32_t*>(&Al[r][c4])     = l;
            split2(x2, x3, h, l);
            *reinterpret_cast<uint32_t*>(&Ah[r][c4 + 2]) = h;
            *reinterpret_cast<uint32_t*>(&Al[r][c4 + 2]) = l;
        }
        // ---- load B tile ----
        if (TB) {
            // B global [N,K]; smem Bt[n][k]
#pragma unroll
            for (int i = 0; i < 2; i++) {
                int r = (tid >> 3) + i * 32;        // n index 0..63
                int c4 = (tid & 7) * 4;             // k index
                int gn = n0 + r, gk = k0 + c4;
                float x0 = 0.f, x1 = 0.f, x2 = 0.f, x3 = 0.f;
                if (gn < p.N) {
                    const float* bp = B + (size_t)gn * p.ldb + gk;
                    if (gk + 3 < p.K && ((((size_t)bp) & 15) == 0)) {
                        float4 v = *reinterpret_cast<const float4*>(bp);
                        x0 = v.x; x1 = v.y; x2 = v.z; x3 = v.w;
                    } else {
                        if (gk     < p.K) x0 = bp[0];
                        if (gk + 1 < p.K) x1 = bp[1];
                        if (gk + 2 < p.K) x2 = bp[2];
                        if (gk + 3 < p.K) x3 = bp[3];
                    }
                }
                uint32_t h, l;
                split2(x0, x1, h, l);
                *reinterpret_cast<uint32_t*>(&Bh[r][c4])     = h;
                *reinterpret_cast<uint32_t*>(&Bl[r][c4])     = l;
                split2(x2, x3, h, l);
                *reinterpret_cast<uint32_t*>(&Bh[r][c4 + 2]) = h;
                *reinterpret_cast<uint32_t*>(&Bl[r][c4 + 2]) = l;
            }
        } else {
            // B global [K,N]; smem Bs[k][n]
#pragma unroll
            for (int i = 0; i < 2; i++) {
                int r = (tid >> 4) + i * 16;        // k index 0..31
                int c4 = (tid & 15) * 4;            // n index
                int gk = k0 + r, gn = n0 + c4;
                float x0 = 0.f, x1 = 0.f, x2 = 0.f, x3 = 0.f;
                if (gk < p.K) {
                    const float* bp = B + (size_t)gk * p.ldb + gn;
                    if (gn + 3 < p.N && ((((size_t)bp) & 15) == 0)) {
                        float4 v = *reinterpret_cast<const float4*>(bp);
                        x0 = v.x; x1 = v.y; x2 = v.z; x3 = v.w;
                    } else {
                        if (gn     < p.N) x0 = bp[0];
                        if (gn + 1 < p.N) x1 = bp[1];
                        if (gn + 2 < p.N) x2 = bp[2];
                        if (gn + 3 < p.N) x3 = bp[3];
                    }
                }
                uint32_t h, l;
                split2(x0, x1, h, l);
                *reinterpret_cast<uint32_t*>(&Bh[r][c4])     = h;
                *reinterpret_cast<uint32_t*>(&Bl[r][c4])     = l;
                split2(x2, x3, h, l);
                *reinterpret_cast<uint32_t*>(&Bh[r][c4 + 2]) = h;
                *reinterpret_cast<uint32_t*>(&Bl[r][c4 + 2]) = l;
            }
        }
        __syncthreads();

#pragma unroll
        for (int ks = 0; ks < BK; ks += 16) {
            uint32_t ah[2][4], al[2][4], bh[4][2], bl[4][2];
            const int lr = lane & 15, lc = (lane >> 4) * 8;
#pragma unroll
            for (int mi = 0; mi < 2; mi++) {
                ldsm4(ah[mi][0], ah[mi][1], ah[mi][2], ah[mi][3], &Ah[wm0 + mi * 16 + lr][ks + lc]);
                ldsm4(al[mi][0], al[mi][1], al[mi][2], al[mi][3], &Al[wm0 + mi * 16 + lr][ks + lc]);
            }
            const int l8 = lane & 7, q = lane >> 3;
#pragma unroll
            for (int np = 0; np < 2; np++) {
                if (TB) {
                    int r = wn0 + np * 16 + l8 + ((q >= 2) ? 8 : 0);
                    int c = ks + ((q & 1) ? 8 : 0);
                    ldsm4(bh[np*2][0], bh[np*2][1], bh[np*2+1][0], bh[np*2+1][1], &Bh[r][c]);
                    ldsm4(bl[np*2][0], bl[np*2][1], bl[np*2+1][0], bl[np*2+1][1], &Bl[r][c]);
                } else {
                    int r = ks + l8 + ((q & 1) ? 8 : 0);
                    int c = wn0 + np * 16 + ((q >= 2) ? 8 : 0);
                    ldsm4t(bh[np*2][0], bh[np*2][1], bh[np*2+1][0], bh[np*2+1][1], &Bh[r][c]);
                    ldsm4t(bl[np*2][0], bl[np*2][1], bl[np*2+1][0], bl[np*2+1][1], &Bl[r][c]);
                }
            }
#pragma unroll
            for (int mi = 0; mi < 2; mi++)
#pragma unroll
                for (int ni = 0; ni < 4; ni++) {
                    mma_bf16(acc[mi][ni], ah[mi], bh[ni]);   // hi*hi
                    mma_bf16(acc[mi][ni], ah[mi], bl[ni]);   // hi*lo
                    mma_bf16(acc[mi][ni], al[mi], bh[ni]);   // lo*hi
                }
        }
        __syncthreads();
    }

    // ---- epilogue ----
#pragma unroll
    for (int mi = 0; mi < 2; mi++)
#pragma unroll
        for (int ni = 0; ni < 4; ni++)
#pragma unroll
            for (int hf = 0; hf < 2; hf++) {
                int gm = m0 + wm0 + mi * 16 + (lane >> 2) + hf * 8;
                if (gm >= p.M) continue;
#pragma unroll
                for (int j = 0; j < 2; j++) {
                    int gn = n0 + wn0 + ni * 8 + (lane & 3) * 2 + j;
                    if (gn >= p.N) continue;
                    float v = acc[mi][ni][hf * 2 + j];
                    if (p.bias) v += p.bias[gn];
                    if (p.res)  v += p.res[(size_t)gm * p.ldc + gn];
                    if (p.gelu) v = 0.5f * v * (1.f + erff(v * 0.70710678118654752f));
                    C[(size_t)gm * p.ldc + gn] = v;
                }
            }
}

// ---------------- elementwise kernels ----------------
__global__ void patchify_k(const float* __restrict__ img, float* __restrict__ P) {
    int bp = blockIdx.x;
    int b = bp / NPATCH, pi = bp % NPATCH;
    int g1 = pi / 24, g2 = pi % 24;
    int tid = threadIdx.x;
#pragma unroll
    for (int j = 0; j < 3; j++) {
        int e = tid + j * 256;                    // 768 = 3*256
        int c = e >> 8, rem = e & 255, p1 = rem >> 4, p2 = rem & 15;
        P[(size_t)bp * DMODEL + e] =
            img[(((size_t)b * 3 + c) * 384 + g1 * 16 + p1) * 384 + g2 * 16 + p2];
    }
}

__global__ void assemble_k(const float* __restrict__ tok, const float* __restrict__ cls,
                           const float* __restrict__ pos, float* __restrict__ X) {
    int bn = blockIdx.x;
    int b = bn / NTOK, n = bn % NTOK;
    int tid = threadIdx.x;
#pragma unroll
    for (int j = 0; j < 3; j++) {
        int e = tid + j * 256;
        float t = (n == 0) ? cls[e] : tok[((size_t)b * NPATCH + (n - 1)) * DMODEL + e];
        X[(size_t)bn * DMODEL + e] = t + pos[(size_t)n * DMODEL + e];
    }
}

__global__ void ln_k(const float* __restrict__ x, float* __restrict__ y,
                     const float* __restrict__ s, const float* __restrict__ b) {
    int row = blockIdx.x, tid = threadIdx.x;
    const float* xp = x + (size_t)row * DMODEL;
    float v[3], sum = 0.f, sq = 0.f;
#pragma unroll
    for (int j = 0; j < 3; j++) { v[j] = xp[tid + j * 256]; sum += v[j]; sq += v[j] * v[j]; }
#pragma unroll
    for (int o = 16; o; o >>= 1) {
        sum += __shfl_xor_sync(0xffffffffu, sum, o);
        sq  += __shfl_xor_sync(0xffffffffu, sq,  o);
    }
    __shared__ float s1[8], s2[8];
    int warp = tid >> 5, lane = tid & 31;
    if (lane == 0) { s1[warp] = sum; s2[warp] = sq; }
    __syncthreads();
    if (warp == 0) {
        sum = (lane < 8) ? s1[lane] : 0.f;
        sq  = (lane < 8) ? s2[lane] : 0.f;
#pragma unroll
        for (int o = 4; o; o >>= 1) {
            sum += __shfl_xor_sync(0xffffffffu, sum, o);
            sq  += __shfl_xor_sync(0xffffffffu, sq,  o);
        }
        if (lane == 0) { s1[0] = sum; s2[0] = sq; }
    }
    __syncthreads();
    float mean = s1[0] * (1.f / DMODEL);
    float var  = s2[0] * (1.f / DMODEL) - mean * mean;
    float rstd = rsqrtf(var + 1e-5f);
    float* yp = y + (size_t)row * DMODEL;
#pragma unroll
    for (int j = 0; j < 3; j++) {
        int i = tid + j * 256;
        yp[i] = (v[j] - mean) * rstd * s[i] + b[i];
    }
}

// cosine-normalize q (with 1/sqrt(DH) folded in) and k; one warp per head
__global__ void qknorm_k(float* __restrict__ Q, float* __restrict__ K) {
    int row = blockIdx.x;
    int warp = threadIdx.x >> 5, lane = threadIdx.x & 31;
    {
        float* q = Q + (size_t)row * DMODEL + warp * DHEAD;
        float a = q[lane], b = q[lane + 32];
        float s = a * a + b * b;
#pragma unroll
        for (int o = 16; o; o >>= 1) s += __shfl_xor_sync(0xffffffffu, s, o);
        float sc = 0.125f / (sqrtf(s) + 1e-6f);        // 1/sqrt(64) folded in
        q[lane] = a * sc; q[lane + 32] = b * sc;
    }
    {
        float* k = K + (size_t)row * DMODEL + warp * DHEAD;
        float a = k[lane], b = k[lane + 32];
        float s = a * a + b * b;
#pragma unroll
        for (int o = 16; o; o >>= 1) s += __shfl_xor_sync(0xffffffffu, s, o);
        float sc = 1.f / (sqrtf(s) + 1e-6f);
        k[lane] = a * sc; k[lane + 32] = b * sc;
    }
}

__global__ void softmax_k(float* __restrict__ S) {
    size_t row = blockIdx.x;
    float* p = S + row * NTOK;
    int tid = threadIdx.x;
    float v[3], mx = -1e30f;
#pragma unroll
    for (int j = 0; j < 3; j++) {
        int i = tid + j * 256;
        v[j] = (i < NTOK) ? p[i] : -1e30f;
        mx = fmaxf(mx, v[j]);
    }
#pragma unroll
    for (int o = 16; o; o >>= 1) mx = fmaxf(mx, __shfl_xor_sync(0xffffffffu, mx, o));
    __shared__ float s1[8];
    int warp = tid >> 5, lane = tid & 31;
    if (lane == 0) s1[warp] = mx;
    __syncthreads();
    if (warp == 0) {
        mx = (lane < 8) ? s1[lane] : -1e30f;
#pragma unroll
        for (int o = 4; o; o >>= 1) mx = fmaxf(mx, __shfl_xor_sync(0xffffffffu, mx, o));
        if (lane == 0) s1[0] = mx;
    }
    __syncthreads();
    mx = s1[0];
    float sum = 0.f;
#pragma unroll
    for (int j = 0; j < 3; j++) { v[j] = __expf(v[j] - mx); sum += v[j]; }
#pragma unroll
    for (int o = 16; o; o >>= 1) sum += __shfl_xor_sync(0xffffffffu, sum, o);
    __shared__ float s2[8];
    if (lane == 0) s2[warp] = sum;
    __syncthreads();
    if (warp == 0) {
        sum = (lane < 8) ? s2[lane] : 0.f;
#pragma unroll
        for (int o = 4; o; o >>= 1) sum += __shfl_xor_sync(0xffffffffu, sum, o);
        if (lane == 0) s2[0] = sum;
    }
    __syncthreads();
    float inv = 1.f / s2[0];
#pragma unroll
    for (int j = 0; j < 3; j++) {
        int i = tid + j * 256;
        if (i < NTOK) p[i] = v[j] * inv;
    }
}

// ---------------- host ----------------
static void rungemm(bool tb, const float* A, const float* B, float* C,
                    int M, int N, int K, int lda, int ldb, int ldc, int batches,
                    int divA, long long sA1, long long sA2,
                    int divB, long long sB1, long long sB2,
                    int divC, long long sC1, long long sC2,
                    const float* bias, const float* res, int gelu) {
    GP p{A, B, C, bias, res, M, N, K, lda, ldb, ldc,
         divA, sA1, sA2, divB, sB1, sB2, divC, sC1, sC2, gelu};
    dim3 grid((N + 63) / 64, (M + 127) / 128, batches);
    if (tb) gemm_k<true ><<<grid, 256>>>(p);
    else    gemm_k<false><<<grid, 256>>>(p);
}

extern "C" void kernel_launch(void* const* d_in, const int* in_sizes, int n_in,
                              void* d_out, int out_size) {
    const float* image  = (const float*)d_in[0];
    const float* conv_w = (const float*)d_in[1];
    const float* conv_b = (const float*)d_in[2];
    const float* pos    = (const float*)d_in[3];
    const float* cls    = (const float*)d_in[4];
    const float* ln1_s  = (const float*)d_in[5];
    const float* ln1_b  = (const float*)d_in[6];
    const float* wq     = (const float*)d_in[7];
    const float* wk     = (const float*)d_in[8];
    const float* wv     = (const float*)d_in[9];
    const float* wo     = (const float*)d_in[10];
    const float* bo     = (const float*)d_in[11];
    const float* ln2_s  = (const float*)d_in[12];
    const float* ln2_b  = (const float*)d_in[13];
    const float* w1     = (const float*)d_in[14];
    const float* b1     = (const float*)d_in[15];
    const float* w2     = (const float*)d_in[16];
    const float* b2     = (const float*)d_in[17];
    const float* wc     = (const float*)d_in[18];
    const float* bc     = (const float*)d_in[19];
    float* out = (float*)d_out;

    float *X, *Y, *Z, *Q, *K, *V, *VH, *Hb, *S;
    cudaGetSymbolAddress((void**)&X,  g_X);
    cudaGetSymbolAddress((void**)&Y,  g_Y);
    cudaGetSymbolAddress((void**)&Z,  g_Z);
    cudaGetSymbolAddress((void**)&Q,  g_Q);
    cudaGetSymbolAddress((void**)&K,  g_K);
    cudaGetSymbolAddress((void**)&V,  g_V);
    cudaGetSymbolAddress((void**)&VH, g_VH);
    cudaGetSymbolAddress((void**)&Hb, g_H);
    cudaGetSymbolAddress((void**)&S,  g_S);

    const long long QS = (long long)NTOK * DMODEL;   // 443136 per-batch stride in Q/K/V
    const long long SS = (long long)NTOK * NTOK;     // 332929 per-(b,h) stride in scores

    // patch embed + assemble
    patchify_k<<<PROWS, 256>>>(image, Hb);
    rungemm(false, Hb, conv_w, Z, PROWS, DMODEL, DMODEL, DMODEL, DMODEL, DMODEL, 1,
            1, 0, 0, 1, 0, 0, 1, 0, 0, conv_b, nullptr, 0);
    assemble_k<<<ROWS, 256>>>(Z, cls, pos, X);

    for (int l = 0; l < NL; l++) {
        const float* WQ = wq + (size_t)l * DMODEL * DMODEL;
        const float* WK = wk + (size_t)l * DMODEL * DMODEL;
        const float* WV = wv + (size_t)l * DMODEL * DMODEL;
        const float* WO = wo + (size_t)l * DMODEL * DMODEL;
        const float* W1 = w1 + (size_t)l * DMODEL * DMLP;
        const float* W2 = w2 + (size_t)l * DMLP * DMODEL;

        ln_k<<<ROWS, 256>>>(X, Y, ln1_s + l * DMODEL, ln1_b + l * DMODEL);

        rungemm(false, Y, WQ, Q, ROWS, DMODEL, DMODEL, DMODEL, DMODEL, DMODEL, 1,
                1, 0, 0, 1, 0, 0, 1, 0, 0, nullptr, nullptr, 0);
        rungemm(false, Y, WK, K, ROWS, DMODEL, DMODEL, DMODEL, DMODEL, DMODEL, 1,
                1, 0, 0, 1, 0, 0, 1, 0, 0, nullptr, nullptr, 0);
        rungemm(false, Y, WV, V, ROWS, DMODEL, DMODEL, DMODEL, DMODEL, DMODEL, 1,
                1, 0, 0, 1, 0, 0, 1, 0, 0, nullptr, nullptr, 0);

        qknorm_k<<<ROWS, 384>>>(Q, K);

        // scores[b,h] = q • k^T   (NT), batched over 384 (b,h)
        rungemm(true, Q, K, S, NTOK, NTOK, DHEAD, DMODEL, DMODEL, NTOK, BATCH * NHEAD,
                NHEAD, QS, DHEAD, NHEAD, QS, DHEAD, 1, SS, 0, nullptr, nullptr, 0);

        softmax_k<<<BATCH * NHEAD * NTOK, 256>>>(S);

        // vh[b,:,h] = A[b,h] @ v[b,:,h]   (NN), batched
        rungemm(false, S, V, VH, NTOK, DHEAD, NTOK, NTOK, DMODEL, DMODEL, BATCH * NHEAD,
                1, SS, 0, NHEAD, QS, DHEAD, NHEAD, QS, DHEAD, nullptr, nullptr, 0);

        // Ynew = Y + vh@Wo + bo   -> X
        rungemm(false, VH, WO, X, ROWS, DMODEL, DMODEL, DMODEL, DMODEL, DMODEL, 1,
                1, 0, 0, 1, 0, 0, 1, 0, 0, bo + l * DMODEL, Y, 0);

        ln_k<<<ROWS, 256>>>(X, Z, ln2_s + l * DMODEL, ln2_b + l * DMODEL);

        // H = gelu(Z@W1 + b1)
        rungemm(false, Z, W1, Hb, ROWS, DMLP, DMODEL, DMODEL, DMLP, DMLP, 1,
                1, 0, 0, 1, 0, 0, 1, 0, 0, b1 + l * DMLP, nullptr, 1);
        // Xnext = Z + H@W2 + b2
        rungemm(false, Hb, W2, X, ROWS, DMODEL, DMLP, DMLP, DMODEL, DMODEL, 1,
                1, 0, 0, 1, 0, 0, 1, 0, 0, b2 + l * DMODEL, Z, 0);
    }

    // classifier on cls tokens: A rows strided by NTOK*DMODEL
    rungemm(false, X, wc, out, BATCH, OUTN, DMODEL, NTOK * DMODEL, OUTN, OUTN, 1,
            1, 0, 0, 1, 0, 0, 1, 0, 0, bc, nullptr, 0);
}

// round 16
// speedup vs baseline: 1.0035x; 1.0035x over previous
#include <cuda_runtime.h>
#include <cuda_bf16.h>
#include <cstdint>
#include <cstdio>

// ---------------- problem constants ----------------
#define NL    12
#define DMODEL 768
#define NHEAD 12
#define DHEAD 64
#define DMLP  3072
#define NTOK  577
#define NPATCH 576
#define BATCH 32
#define ROWS  (BATCH*NTOK)     // 18464
#define PROWS (BATCH*NPATCH)   // 18432
#define OUTN  1000

// ---------------- scratch (device globals; no allocation allowed) ----------------
__device__ float g_X [ROWS*DMODEL];
__device__ float g_Y [ROWS*DMODEL];
__device__ float g_Z [ROWS*DMODEL];
__device__ float g_Q [ROWS*DMODEL];
__device__ float g_K [ROWS*DMODEL];
__device__ float g_V [ROWS*DMODEL];
__device__ float g_VH[ROWS*DMODEL];
__device__ float g_H [ROWS*DMLP];              // also reused as patch buffer
__device__ float g_S [127844736UL];            // 32*12*577*577 scores

// ---------------- GEMM params ----------------
struct GP {
    const float *A, *B; float *C;
    const float *bias, *res;
    int M, N, K, lda, ldb, ldc;
    int divA; long long sA1, sA2;
    int divB; long long sB1, sB2;
    int divC; long long sC1, sC2;
    int gelu;
};

// ---------------- PTX helpers ----------------
__device__ __forceinline__ void ldsm4(uint32_t &r0, uint32_t &r1, uint32_t &r2, uint32_t &r3,
                                      const __nv_bfloat16* p) {
    uint32_t a = (uint32_t)__cvta_generic_to_shared(p);
    asm volatile("ldmatrix.sync.aligned.m8n8.x4.shared.b16 {%0,%1,%2,%3},[%4];\n"
                 : "=r"(r0), "=r"(r1), "=r"(r2), "=r"(r3) : "r"(a));
}
__device__ __forceinline__ void ldsm4t(uint32_t &r0, uint32_t &r1, uint32_t &r2, uint32_t &r3,
                                       const __nv_bfloat16* p) {
    uint32_t a = (uint32_t)__cvta_generic_to_shared(p);
    asm volatile("ldmatrix.sync.aligned.m8n8.x4.trans.shared.b16 {%0,%1,%2,%3},[%4];\n"
                 : "=r"(r0), "=r"(r1), "=r"(r2), "=r"(r3) : "r"(a));
}
__device__ __forceinline__ void mma_bf16(float c[4], const uint32_t a[4], const uint32_t b[2]) {
    asm volatile("mma.sync.aligned.m16n8k16.row.col.f32.bf16.bf16.f32 "
                 "{%0,%1,%2,%3},{%4,%5,%6,%7},{%8,%9},{%0,%1,%2,%3};\n"
                 : "+f"(c[0]), "+f"(c[1]), "+f"(c[2]), "+f"(c[3])
                 : "r"(a[0]), "r"(a[1]), "r"(a[2]), "r"(a[3]), "r"(b[0]), "r"(b[1]));
}
// split fp32 pair into bf16 hi/lo packed u32s
__device__ __forceinline__ void split2(float x0, float x1, uint32_t &hi, uint32_t &lo) {
    __nv_bfloat16 h0 = __float2bfloat16(x0);
    __nv_bfloat16 h1 = __float2bfloat16(x1);
    float r0 = x0 - __bfloat162float(h0);
    float r1 = x1 - __bfloat162float(h1);
    __nv_bfloat162 hv = __halves2bfloat162(h0, h1);
    __nv_bfloat162 lv = __halves2bfloat162(__float2bfloat16(r0), __float2bfloat16(r1));
    hi = *reinterpret_cast<uint32_t*>(&hv);
    lo = *reinterpret_cast<uint32_t*>(&lv);
}

// ---------------- GEMM kernel: C = A*B (+bias)(+res)(gelu), bf16x3 precision ----------------
// TB=false: B global is [K,N] row-major (NN).  TB=true: B global is [N,K] row-major (NT, C=A*B^T)
template<bool TB>
__global__ void __launch_bounds__(256) gemm_k(GP p) {
    constexpr int BM = 128, BN = 64, BK = 32;
    __shared__ alignas(16) __nv_bfloat16 Ah[BM][BK + 8];
    __shared__ alignas(16) __nv_bfloat16 Al[BM][BK + 8];
    constexpr int BR  = TB ? BN : BK;
    constexpr int BCW = TB ? (BK + 8) : (BN + 8);
    __shared__ alignas(16) __nv_bfloat16 Bh[BR][BCW];
    __shared__ alignas(16) __nv_bfloat16 Bl[BR][BCW];

    const int tid = threadIdx.x, lane = tid & 31, warp = tid >> 5;
    const int wm0 = (warp & 3) * 32, wn0 = (warp >> 2) * 32;
    const int n0 = blockIdx.x * BN, m0 = blockIdx.y * BM;
    const int z = blockIdx.z;

    const float* A = p.A + (long long)(z / p.divA) * p.sA1 + (long long)(z % p.divA) * p.sA2;
    const float* B = p.B + (long long)(z / p.divB) * p.sB1 + (long long)(z % p.divB) * p.sB2;
    float*       C = p.C + (long long)(z / p.divC) * p.sC1 + (long long)(z % p.divC) * p.sC2;

    float acc[2][4][4];
#pragma unroll
    for (int a = 0; a < 2; a++)
#pragma unroll
        for (int b = 0; b < 4; b++)
#pragma unroll
            for (int c = 0; c < 4; c++) acc[a][b][c] = 0.f;

    for (int k0 = 0; k0 < p.K; k0 += BK) {
        // ---- load A tile [BM][BK] ----
#pragma unroll
        for (int i = 0; i < 4; i++) {
            int r = (tid >> 3) + i * 32;
            int c4 = (tid & 7) * 4;
            int gm = m0 + r, gk = k0 + c4;
            float x0 = 0.f, x1 = 0.f, x2 = 0.f, x3 = 0.f;
            if (gm < p.M) {
                const float* ap = A + (size_t)gm * p.lda + gk;
                if (gk + 3 < p.K && ((((size_t)ap) & 15) == 0)) {
                    float4 v = *reinterpret_cast<const float4*>(ap);
                    x0 = v.x; x1 = v.y; x2 = v.z; x3 = v.w;
                } else {
                    if (gk     < p.K) x0 = ap[0];
                    if (gk + 1 < p.K) x1 = ap[1];
                    if (gk + 2 < p.K) x2 = ap[2];
                    if (gk + 3 < p.K) x3 = ap[3];
                }
            }
            uint32_t h, l;
            split2(x0, x1, h, l);
            *reinterpret_cast<uint32_t*>(&Ah[r][c4])     = h;
            *reinterpret_cast<uint32_t*>(&Al[r][c4])     = l;
            split2(x2, x3, h, l);
            *reinterpret_cast<uint32_t*>(&Ah[r][c4 + 2]) = h;
            *reinterpret_cast<uint32_t*>(&Al[r][c4 + 2]) = l;
        }
        // ---- load B tile ----
        if (TB) {
            // B global [N,K]; smem Bt[n][k]
#pragma unroll
            for (int i = 0; i < 2; i++) {
                int r = (tid >> 3) + i * 32;        // n index 0..63
                int c4 = (tid & 7) * 4;             // k index
                int gn = n0 + r, gk = k0 + c4;
                float x0 = 0.f, x1 = 0.f, x2 = 0.f, x3 = 0.f;
                if (gn < p.N) {
                    const float* bp = B + (size_t)gn * p.ldb + gk;
                    if (gk + 3 < p.K && ((((size_t)bp) & 15) == 0)) {
                        float4 v = *reinterpret_cast<const float4*>(bp);
                        x0 = v.x; x1 = v.y; x2 = v.z; x3 = v.w;
                    } else {
                        if (gk     < p.K) x0 = bp[0];
                        if (gk + 1 < p.K) x1 = bp[1];
                        if (gk + 2 < p.K) x2 = bp[2];
                        if (gk + 3 < p.K) x3 = bp[3];
                    }
                }
                uint32_t h, l;
                split2(x0, x1, h, l);
                *reinterpret_cast<uint32_t*>(&Bh[r][c4])     = h;
                *reinterpret_cast<uint32_t*>(&Bl[r][c4])     = l;
                split2(x2, x3, h, l);
                *reinterpret_cast<uint32_t*>(&Bh[r][c4 + 2]) = h;
                *reinterpret_cast<uint32_t*>(&Bl[r][c4 + 2]) = l;
            }
        } else {
            // B global [K,N]; smem Bs[k][n]
#pragma unroll
            for (int i = 0; i < 2; i++) {
                int r = (tid >> 4) + i * 16;        // k index 0..31
                int c4 = (tid & 15) * 4;            // n index
                int gk = k0 + r, gn = n0 + c4;
                float x0 = 0.f, x1 = 0.f, x2 = 0.f, x3 = 0.f;
                if (gk < p.K) {
                    const float* bp = B + (size_t)gk * p.ldb + gn;
                    if (gn + 3 < p.N && ((((size_t)bp) & 15) == 0)) {
                        float4 v = *reinterpret_cast<const float4*>(bp);
                        x0 = v.x; x1 = v.y; x2 = v.z; x3 = v.w;
                    } else {
                        if (gn     < p.N) x0 = bp[0];
                        if (gn + 1 < p.N) x1 = bp[1];
                        if (gn + 2 < p.N) x2 = bp[2];
                        if (gn + 3 < p.N) x3 = bp[3];
                    }
                }
                uint32_t h, l;
                split2(x0, x1, h, l);
                *reinterpret_cast<uint32_t*>(&Bh[r][c4])     = h;
                *reinterpret_cast<uint32_t*>(&Bl[r][c4])     = l;
                split2(x2, x3, h, l);
                *reinterpret_cast<uint32_t*>(&Bh[r][c4 + 2]) = h;
                *reinterpret_cast<uint32_t*>(&Bl[r][c4 + 2]) = l;
            }
        }
        __syncthreads();

#pragma unroll
        for (int ks = 0; ks < BK; ks += 16) {
            uint32_t ah[2][4], al[2][4], bh[4][2], bl[4][2];
            const int lr = lane & 15, lc = (lane >> 4) * 8;
#pragma unroll
            for (int mi = 0; mi < 2; mi++) {
                ldsm4(ah[mi][0], ah[mi][1], ah[mi][2], ah[mi][3], &Ah[wm0 + mi * 16 + lr][ks + lc]);
                ldsm4(al[mi][0], al[mi][1], al[mi][2], al[mi][3], &Al[wm0 + mi * 16 + lr][ks + lc]);
            }
            const int l8 = lane & 7, q = lane >> 3;
#pragma unroll
            for (int np = 0; np < 2; np++) {
                if (TB) {
                    int r = wn0 + np * 16 + l8 + ((q >= 2) ? 8 : 0);
                    int c = ks + ((q & 1) ? 8 : 0);
                    ldsm4(bh[np*2][0], bh[np*2][1], bh[np*2+1][0], bh[np*2+1][1], &Bh[r][c]);
                    ldsm4(bl[np*2][0], bl[np*2][1], bl[np*2+1][0], bl[np*2+1][1], &Bl[r][c]);
                } else {
                    int r = ks + l8 + ((q & 1) ? 8 : 0);
                    int c = wn0 + np * 16 + ((q >= 2) ? 8 : 0);
                    ldsm4t(bh[np*2][0], bh[np*2][1], bh[np*2+1][0], bh[np*2+1][1], &Bh[r][c]);
                    ldsm4t(bl[np*2][0], bl[np*2][1], bl[np*2+1][0], bl[np*2+1][1], &Bl[r][c]);
                }
            }
#pragma unroll
            for (int mi = 0; mi < 2; mi++)
#pragma unroll
                for (int ni = 0; ni < 4; ni++) {
                    mma_bf16(acc[mi][ni], ah[mi], bh[ni]);   // hi*hi
                    mma_bf16(acc[mi][ni], ah[mi], bl[ni]);   // hi*lo
                    mma_bf16(acc[mi][ni], al[mi], bh[ni]);   // lo*hi
                }
        }
        __syncthreads();
    }

    // ---- epilogue ----
#pragma unroll
    for (int mi = 0; mi < 2; mi++)
#pragma unroll
        for (int ni = 0; ni < 4; ni++)
#pragma unroll
            for (int hf = 0; hf < 2; hf++) {
                int gm = m0 + wm0 + mi * 16 + (lane >> 2) + hf * 8;
                if (gm >= p.M) continue;
#pragma unroll
                for (int j = 0; j < 2; j++) {
                    int gn = n0 + wn0 + ni * 8 + (lane & 3) * 2 + j;
                    if (gn >= p.N) continue;
                    float v = acc[mi][ni][hf * 2 + j];
                    if (p.bias) v += p.bias[gn];
                    if (p.res)  v += p.res[(size_t)gm * p.ldc + gn];
                    if (p.gelu) v = 0.5f * v * (1.f + erff(v * 0.70710678118654752f));
                    C[(size_t)gm * p.ldc + gn] = v;
                }
            }
}

// ---------------- elementwise kernels ----------------
__global__ void patchify_k(const float* __restrict__ img, float* __restrict__ P) {
    int bp = blockIdx.x;
    int b = bp / NPATCH, pi = bp % NPATCH;
    int g1 = pi / 24, g2 = pi % 24;
    int tid = threadIdx.x;
#pragma unroll
    for (int j = 0; j < 3; j++) {
        int e = tid + j * 256;                    // 768 = 3*256
        int c = e >> 8, rem = e & 255, p1 = rem >> 4, p2 = rem & 15;
        P[(size_t)bp * DMODEL + e] =
            img[(((size_t)b * 3 + c) * 384 + g1 * 16 + p1) * 384 + g2 * 16 + p2];
    }
}

__global__ void assemble_k(const float* __restrict__ tok, const float* __restrict__ cls,
                           const float* __restrict__ pos, float* __restrict__ X) {
    int bn = blockIdx.x;
    int b = bn / NTOK, n = bn % NTOK;
    int tid = threadIdx.x;
#pragma unroll
    for (int j = 0; j < 3; j++) {
        int e = tid + j * 256;
        float t = (n == 0) ? cls[e] : tok[((size_t)b * NPATCH + (n - 1)) * DMODEL + e];
        X[(size_t)bn * DMODEL + e] = t + pos[(size_t)n * DMODEL + e];
    }
}

__global__ void ln_k(const float* __restrict__ x, float* __restrict__ y,
                     const float* __restrict__ s, const float* __restrict__ b) {
    int row = blockIdx.x, tid = threadIdx.x;
    const float* xp = x + (size_t)row * DMODEL;
    float v[3], sum = 0.f, sq = 0.f;
#pragma unroll
    for (int j = 0; j < 3; j++) { v[j] = xp[tid + j * 256]; sum += v[j]; sq += v[j] * v[j]; }
#pragma unroll
    for (int o = 16; o; o >>= 1) {
        sum += __shfl_xor_sync(0xffffffffu, sum, o);
        sq  += __shfl_xor_sync(0xffffffffu, sq,  o);
    }
    __shared__ float s1[8], s2[8];
    int warp = tid >> 5, lane = tid & 31;
    if (lane == 0) { s1[warp] = sum; s2[warp] = sq; }
    __syncthreads();
    if (warp == 0) {
        sum = (lane < 8) ? s1[lane] : 0.f;
        sq  = (lane < 8) ? s2[lane] : 0.f;
#pragma unroll
        for (int o = 4; o; o >>= 1) {
            sum += __shfl_xor_sync(0xffffffffu, sum, o);
            sq  += __shfl_xor_sync(0xffffffffu, sq,  o);
        }
        if (lane == 0) { s1[0] = sum; s2[0] = sq; }
    }
    __syncthreads();
    float mean = s1[0] * (1.f / DMODEL);
    float var  = s2[0] * (1.f / DMODEL) - mean * mean;
    float rstd = rsqrtf(var + 1e-5f);
    float* yp = y + (size_t)row * DMODEL;
#pragma unroll
    for (int j = 0; j < 3; j++) {
        int i = tid + j * 256;
        yp[i] = (v[j] - mean) * rstd * s[i] + b[i];
    }
}

// cosine-normalize q (with 1/sqrt(DH) folded in) and k; one warp per head
__global__ void qknorm_k(float* __restrict__ Q, float* __restrict__ K) {
    int row = blockIdx.x;
    int warp = threadIdx.x >> 5, lane = threadIdx.x & 31;
    {
        float* q = Q + (size_t)row * DMODEL + warp * DHEAD;
        float a = q[lane], b = q[lane + 32];
        float s = a * a + b * b;
#pragma unroll
        for (int o = 16; o; o >>= 1) s += __shfl_xor_sync(0xffffffffu, s, o);
        float sc = 0.125f / (sqrtf(s) + 1e-6f);        // 1/sqrt(64) folded in
        q[lane] = a * sc; q[lane + 32] = b * sc;
    }
    {
        float* k = K + (size_t)row * DMODEL + warp * DHEAD;
        float a = k[lane], b = k[lane + 32];
        float s = a * a + b * b;
#pragma unroll
        for (int o = 16; o; o >>= 1) s += __shfl_xor_sync(0xffffffffu, s, o);
        float sc = 1.f / (sqrtf(s) + 1e-6f);
        k[lane] = a * sc; k[lane + 32] = b * sc;
    }
}

__global__ void softmax_k(float* __restrict__ S) {
    size_t row = blockIdx.x;
    float* p = S + row * NTOK;
    int tid = threadIdx.x;
    float v[3], mx = -1e30f;
#pragma unroll
    for (int j = 0; j < 3; j++) {
        int i = tid + j * 256;
        v[j] = (i < NTOK) ? p[i] : -1e30f;
        mx = fmaxf(mx, v[j]);
    }
#pragma unroll
    for (int o = 16; o; o >>= 1) mx = fmaxf(mx, __shfl_xor_sync(0xffffffffu, mx, o));
    __shared__ float s1[8];
    int warp = tid >> 5, lane = tid & 31;
    if (lane == 0) s1[warp] = mx;
    __syncthreads();
    if (warp == 0) {
        mx = (lane < 8) ? s1[lane] : -1e30f;
#pragma unroll
        for (int o = 4; o; o >>= 1) mx = fmaxf(mx, __shfl_xor_sync(0xffffffffu, mx, o));
        if (lane == 0) s1[0] = mx;
    }
    __syncthreads();
    mx = s1[0];
    float sum = 0.f;
#pragma unroll
    for (int j = 0; j < 3; j++) { v[j] = __expf(v[j] - mx); sum += v[j]; }
#pragma unroll
    for (int o = 16; o; o >>= 1) sum += __shfl_xor_sync(0xffffffffu, sum, o);
    __shared__ float s2[8];
    if (lane == 0) s2[warp] = sum;
    __syncthreads();
    if (warp == 0) {
        sum = (lane < 8) ? s2[lane] : 0.f;
#pragma unroll
        for (int o = 4; o; o >>= 1) sum += __shfl_xor_sync(0xffffffffu, sum, o);
        if (lane == 0) s2[0] = sum;
    }
    __syncthreads();
    float inv = 1.f / s2[0];
#pragma unroll
    for (int j = 0; j < 3; j++) {
        int i = tid + j * 256;
        if (i < NTOK) p[i] = v[j] * inv;
    }
}

// ---------------- host ----------------
static void rungemm(bool tb, const float* A, const float* B, float* C,
                    int M, int N, int K, int lda, int ldb, int ldc, int batches,
                    int divA, long long sA1, long long sA2,
                    int divB, long long sB1, long long sB2,
                    int divC, long long sC1, long long sC2,
                    const float* bias, const float* res, int gelu) {
    GP p{A, B, C, bias, res, M, N, K, lda, ldb, ldc,
         divA, sA1, sA2, divB, sB1, sB2, divC, sC1, sC2, gelu};
    dim3 grid((N + 63) / 64, (M + 127) / 128, batches);
    if (tb) gemm_k<true ><<<grid, 256>>>(p);
    else    gemm_k<false><<<grid, 256>>>(p);
}

extern "C" void kernel_launch(void* const* d_in, const int* in_sizes, int n_in,
                              void* d_out, int out_size) {
    const float* image  = (const float*)d_in[0];
    const float* conv_w = (const float*)d_in[1];
    const float* conv_b = (const float*)d_in[2];
    const float* pos    = (const float*)d_in[3];
    const float* cls    = (const float*)d_in[4];
    const float* ln1_s  = (const float*)d_in[5];
    const float* ln1_b  = (const float*)d_in[6];
    const float* wq     = (const float*)d_in[7];
    const float* wk     = (const float*)d_in[8];
    const float* wv     = (const float*)d_in[9];
    const float* wo     = (const float*)d_in[10];
    const float* bo     = (const float*)d_in[11];
    const float* ln2_s  = (const float*)d_in[12];
    const float* ln2_b  = (const float*)d_in[13];
    const float* w1     = (const float*)d_in[14];
    const float* b1     = (const float*)d_in[15];
    const float* w2     = (const float*)d_in[16];
    const float* b2     = (const float*)d_in[17];
    const float* wc     = (const float*)d_in[18];
    const float* bc     = (const float*)d_in[19];
    float* out = (float*)d_out;

    float *X, *Y, *Z, *Q, *K, *V, *VH, *Hb, *S;
    cudaGetSymbolAddress((void**)&X,  g_X);
    cudaGetSymbolAddress((void**)&Y,  g_Y);
    cudaGetSymbolAddress((void**)&Z,  g_Z);
    cudaGetSymbolAddress((void**)&Q,  g_Q);
    cudaGetSymbolAddress((void**)&K,  g_K);
    cudaGetSymbolAddress((void**)&V,  g_V);
    cudaGetSymbolAddress((void**)&VH, g_VH);
    cudaGetSymbolAddress((void**)&Hb, g_H);
    cudaGetSymbolAddress((void**)&S,  g_S);

    const long long QS = (long long)NTOK * DMODEL;   // 443136 per-batch stride in Q/K/V
    const long long SS = (long long)NTOK * NTOK;     // 332929 per-(b,h) stride in scores

    // patch embed + assemble
    patchify_k<<<PROWS, 256>>>(image, Hb);
    rungemm(false, Hb, conv_w, Z, PROWS, DMODEL, DMODEL, DMODEL, DMODEL, DMODEL, 1,
            1, 0, 0, 1, 0, 0, 1, 0, 0, conv_b, nullptr, 0);
    assemble_k<<<ROWS, 256>>>(Z, cls, pos, X);

    for (int l = 0; l < NL; l++) {
        const float* WQ = wq + (size_t)l * DMODEL * DMODEL;
        const float* WK = wk + (size_t)l * DMODEL * DMODEL;
        const float* WV = wv + (size_t)l * DMODEL * DMODEL;
        const float* WO = wo + (size_t)l * DMODEL * DMODEL;
        const float* W1 = w1 + (size_t)l * DMODEL * DMLP;
        const float* W2 = w2 + (size_t)l * DMLP * DMODEL;

        ln_k<<<ROWS, 256>>>(X, Y, ln1_s + l * DMODEL, ln1_b + l * DMODEL);

        rungemm(false, Y, WQ, Q, ROWS, DMODEL, DMODEL, DMODEL, DMODEL, DMODEL, 1,
                1, 0, 0, 1, 0, 0, 1, 0, 0, nullptr, nullptr, 0);
        rungemm(false, Y, WK, K, ROWS, DMODEL, DMODEL, DMODEL, DMODEL, DMODEL, 1,
                1, 0, 0, 1, 0, 0, 1, 0, 0, nullptr, nullptr, 0);
        rungemm(false, Y, WV, V, ROWS, DMODEL, DMODEL, DMODEL, DMODEL, DMODEL, 1,
                1, 0, 0, 1, 0, 0, 1, 0, 0, nullptr, nullptr, 0);

        qknorm_k<<<ROWS, 384>>>(Q, K);

        // scores[b,h] = q • k^T   (NT), batched over 384 (b,h)
        rungemm(true, Q, K, S, NTOK, NTOK, DHEAD, DMODEL, DMODEL, NTOK, BATCH * NHEAD,
                NHEAD, QS, DHEAD, NHEAD, QS, DHEAD, 1, SS, 0, nullptr, nullptr, 0);

        softmax_k<<<BATCH * NHEAD * NTOK, 256>>>(S);

        // vh[b,:,h] = A[b,h] @ v[b,:,h]   (NN), batched
        rungemm(false, S, V, VH, NTOK, DHEAD, NTOK, NTOK, DMODEL, DMODEL, BATCH * NHEAD,
                1, SS, 0, NHEAD, QS, DHEAD, NHEAD, QS, DHEAD, nullptr, nullptr, 0);

        // Ynew = Y + vh@Wo + bo   -> X
        rungemm(false, VH, WO, X, ROWS, DMODEL, DMODEL, DMODEL, DMODEL, DMODEL, 1,
                1, 0, 0, 1, 0, 0, 1, 0, 0, bo + l * DMODEL, Y, 0);

        ln_k<<<ROWS, 256>>>(X, Z, ln2_s + l * DMODEL, ln2_b + l * DMODEL);

        // H = gelu(Z@W1 + b1)
        rungemm(false, Z, W1, Hb, ROWS, DMLP, DMODEL, DMODEL, DMLP, DMLP, 1,
                1, 0, 0, 1, 0, 0, 1, 0, 0, b1 + l * DMLP, nullptr, 1);
        // Xnext = Z + H@W2 + b2
        rungemm(false, Hb, W2, X, ROWS, DMODEL, DMLP, DMLP, DMODEL, DMODEL, 1,
                1, 0, 0, 1, 0, 0, 1, 0, 0, b2 + l * DMODEL, Z, 0);
    }

    // classifier on cls tokens: A rows strided by NTOK*DMODEL
    rungemm(false, X, wc, out, BATCH, OUTN, DMODEL, NTOK * DMODEL, OUTN, OUTN, 1,
            1, 0, 0, 1, 0, 0, 1, 0, 0, bc, nullptr, 0);
}